// round 17
// baseline (speedup 1.0000x reference)
#include <cuda_runtime.h>
#include <cuda_bf16.h>
#include <cstdint>

#define BATCH 128
#define NIN   1024
#define NOUT  512
#define JT    64
#define NJT   8
#define NCH   37             // 36 chunks of 28 i-rows + 1 of 16 ; grid 8*37 = 296 = 148*2
#define NBLK  296
#define NTHR  (NBLK * 256)
#define E0    2.1245f
#define LN2   0.69314718f
#define OUTF4 16384
#define ROWF4 128
#define KP    16             // smem K-pitch in u32 (32 bf16 = 8 i-rows)

// XOR swizzle: conflict-free for both STS.64 staging and fragment LDS.32
#define SWZ(row, c) (((row) * KP) + ((c) ^ (((row) & 7) << 1)))

__device__ int          g_max_bits;              // zero-init; monotone -> replay-stable
__device__ unsigned int g_gate1, g_gate2;        // monotone ticket counters (never reset)
__device__ float        g_partial[NCH * BATCH * NOUT];

__device__ __forceinline__ float ex2f_(float x) {
    float y; asm("ex2.approx.f32 %0, %1;" : "=f"(y) : "f"(x)); return y;
}
__device__ __forceinline__ float lg2f_(float x) {
    float y; asm("lg2.approx.f32 %0, %1;" : "=f"(y) : "f"(x)); return y;
}
__device__ __forceinline__ uint32_t pkbf2(float lo, float hi) {
    uint32_t r; asm("cvt.rn.bf16x2.f32 %0, %1, %2;" : "=r"(r) : "f"(hi), "f"(lo)); return r;
}
__device__ __forceinline__ void mma16816(float* d, const uint32_t* a, const uint32_t* b) {
    asm volatile(
        "mma.sync.aligned.m16n8k16.row.col.f32.bf16.bf16.f32 "
        "{%0,%1,%2,%3}, {%4,%5,%6,%7}, {%8,%9}, {%0,%1,%2,%3};"
        : "+f"(d[0]), "+f"(d[1]), "+f"(d[2]), "+f"(d[3])
        : "r"(a[0]), "r"(a[1]), "r"(a[2]), "r"(a[3]), "r"(b[0]), "r"(b[1]));
}

// Monotone-ticket global barrier (replay-safe, no reset needed).
__device__ __forceinline__ void global_gate(unsigned int* ctr, int tid) {
    __syncthreads();
    if (tid == 0) {
        __threadfence();
        unsigned int t = atomicAdd(ctr, 1u);
        unsigned int target = (t / NBLK + 1u) * NBLK;
        while (*reinterpret_cast<volatile unsigned int*>(ctr) < target)
            __nanosleep(32);
    }
    __syncthreads();
    __threadfence();
}

__device__ __forceinline__ void split4(float C0, float C1, float C2, float C3,
                                       uint32_t& h01, uint32_t& h23,
                                       uint32_t& l01, uint32_t& l23) {
    h01 = pkbf2(C0, C1); h23 = pkbf2(C2, C3);
    float f0 = __uint_as_float(h01 << 16);
    float f1 = __uint_as_float(h01 & 0xFFFF0000u);
    float f2 = __uint_as_float(h23 << 16);
    float f3 = __uint_as_float(h23 & 0xFFFF0000u);
    l01 = pkbf2(C0 - f0, C1 - f1); l23 = pkbf2(C2 - f2, C3 - f3);
}

// ---- register prefetch for one slab (ROWS in {8,4}); x read directly ----
template<int ROWS>
__device__ __forceinline__ void slab_load(
    const float* __restrict__ x,
    const float* __restrict__ w_pos, const float* __restrict__ w_neg,
    const float* __restrict__ n_param,
    int iG0, int j0, int tid,
    float* xr, float* wpr, float* wnr, float2* npr)
{
    #pragma unroll
    for (int r = 0; r < (ROWS * 128) / 256; r++) {
        int idx = r * 256 + tid;
        int b = idx / ROWS, i = idx % ROWS;     // i-fast: 4 sectors/warp
        xr[r] = x[b * NIN + iG0 + i];
    }
    #pragma unroll
    for (int r = 0; r < (ROWS * 64) / 256; r++) {
        int idx = r * 256 + tid;
        int ig = iG0 + (idx >> 6), jg = j0 + (idx & 63);
        wpr[r] = w_pos[ig * NOUT + jg];
        wnr[r] = w_neg[ig * NOUT + jg];
        npr[r] = reinterpret_cast<const float2*>(n_param)[ig * NOUT + jg];
    }
}

// ---- convert + swizzled STS for one slab ----
template<int ROWS>
__device__ __forceinline__ void slab_store(
    uint32_t* Ah, uint32_t* Al, uint32_t* Bh, uint32_t* Bl,
    int tid, float cG,
    const float* xr, const float* wpr, const float* wnr, const float2* npr)
{
    #pragma unroll
    for (int r = 0; r < (ROWS * 128) / 256; r++) {
        int idx = r * 256 + tid;
        int b = idx / ROWS, i = idx % ROWS;
        float lv = fmaxf(lg2f_(2.0f * fminf(fmaxf(xr[r], 0.0f), 1.0f)), -8.0f);
        float p0 = ex2f_(E0 * lv);
        float L  = lv * LN2;
        float p1 = p0 * L;
        float p2 = p1 * (0.5f * L);
        float p3 = p2 * (0.33333333f * L);
        uint32_t h01, h23, l01, l23;
        split4(p0, p1, p2, p3, h01, h23, l01, l23);
        int widx = SWZ(b, 2 * i);
        *reinterpret_cast<uint2*>(Ah + widx) = make_uint2(h01, h23);
        *reinterpret_cast<uint2*>(Al + widx) = make_uint2(l01, l23);
    }
    #pragma unroll
    for (int r = 0; r < (ROWS * 64) / 256; r++) {
        int idx = r * 256 + tid;
        int j = idx & 63, i = idx >> 6;
        float cp = 0.5f * (fabsf(wpr[r]) + cG);
        float cn = 0.5f * (fabsf(wnr[r]) + cG);
        float ep = lg2f_(npr[r].x) + 1.0f - E0;
        float en = lg2f_(npr[r].y) + 1.0f - E0;
        float ep2 = ep * ep, en2 = en * en;
        uint32_t h01, h23, l01, l23;
        split4(cp - cn, cp * ep - cn * en,
               cp * ep2 - cn * en2, cp * ep2 * ep - cn * en2 * en,
               h01, h23, l01, l23);
        int widx = SWZ(j, 2 * i);
        *reinterpret_cast<uint2*>(Bh + widx) = make_uint2(h01, h23);
        *reinterpret_cast<uint2*>(Bl + widx) = make_uint2(l01, l23);
    }
}

// ---- HMMA over one staged slab ----
template<int ROWS>
__device__ __forceinline__ void slab_mma(
    const uint32_t* Ah, const uint32_t* Al,
    const uint32_t* Bh, const uint32_t* Bl,
    int wid, int g, int q, float (*acc)[4])
{
    constexpr int NK = ROWS / 4;
    const int arow = 16 * wid + g;
    #pragma unroll
    for (int s = 0; s < NK; s++) {
        int a0 = SWZ(arow, 8 * s + q);
        int a1 = SWZ(arow, 8 * s + q + 4);
        uint32_t ah[4] = {Ah[a0], Ah[a0 + 8 * KP], Ah[a1], Ah[a1 + 8 * KP]};
        uint32_t al[4] = {Al[a0], Al[a0 + 8 * KP], Al[a1], Al[a1 + 8 * KP]};
        #pragma unroll
        for (int nt = 0; nt < 8; nt++) {
            int b0 = SWZ(8 * nt + g, 8 * s + q);
            int b1 = SWZ(8 * nt + g, 8 * s + q + 4);
            uint32_t bh[2] = {Bh[b0], Bh[b1]};
            uint32_t bl[2] = {Bl[b0], Bl[b1]};
            mma16816(acc[nt], ah, bh);
            mma16816(acc[nt], ah, bl);
            mma16816(acc[nt], al, bh);
        }
    }
}

// ---------------------------------------------------------------------------
// Single persistent kernel: prologue (per-tile max|w| only) -> gate1 ->
// double-buffered tensor-core GEMM (x converted in-CTA) -> partials ->
// bias prefetch -> gate2 -> all-CTA distributed reduce.
// ---------------------------------------------------------------------------
__global__ void __launch_bounds__(256, 2)
k_all(const float* __restrict__ x,
      const float* __restrict__ w_pos, const float* __restrict__ w_neg,
      const float* __restrict__ n_param,
      const float* __restrict__ b_pos, const float* __restrict__ b_neg,
      float4* __restrict__ out) {
    __shared__ __align__(16) uint32_t Ah[2][128 * KP], Al[2][128 * KP];  // 32 KB
    __shared__ __align__(16) uint32_t Bh[2][64 * KP],  Bl[2][64 * KP];   // 16 KB

    const int tid = threadIdx.x;
    const int col = blockIdx.x;
    const int ch  = blockIdx.y;
    const int bid = ch * NJT + col;
    const int j0  = col * JT;
    const int i0  = ch * 28;
    const int rows = (ch < 36) ? 28 : 16;

    // ---- prologue: per-tile max|w| (covers grid exactly once; warms L2) ----
    {
        const float4* wp4 = reinterpret_cast<const float4*>(w_pos);
        const float4* wn4 = reinterpret_cast<const float4*>(w_neg);
        float m = 0.5f;   // bias value always present
        for (int idx = tid; idx < rows * 16; idx += 256) {
            int a = (i0 + (idx >> 4)) * ROWF4 + (j0 >> 2) + (idx & 15);
            float4 A = wp4[a], B = wn4[a];
            m = fmaxf(m, fmaxf(fmaxf(fabsf(A.x), fabsf(A.y)), fmaxf(fabsf(A.z), fabsf(A.w))));
            m = fmaxf(m, fmaxf(fmaxf(fabsf(B.x), fabsf(B.y)), fmaxf(fabsf(B.z), fabsf(B.w))));
        }
        #pragma unroll
        for (int o = 16; o; o >>= 1) m = fmaxf(m, __shfl_xor_sync(0xffffffffu, m, o));
        float* sred = reinterpret_cast<float*>(&Bh[0][0]);   // reused pre-gate only
        const int lane = tid & 31, w = tid >> 5;
        if (lane == 0) sred[w] = m;
        __syncthreads();
        if (tid == 0) {
            #pragma unroll
            for (int i = 1; i < 8; i++) m = fmaxf(m, sred[i]);
            atomicMax(&g_max_bits, __float_as_int(m));
        }
    }
    global_gate(&g_gate1, tid);
    const float cG = __int_as_float(g_max_bits) * (1.0f / 9.0f);

    // ---- double-buffered tensor-core GEMM over this CTA's tile ----
    const int wid = tid >> 5;
    const int g   = (tid & 31) >> 2;
    const int q   = tid & 3;
    float acc[8][4];
    #pragma unroll
    for (int nt = 0; nt < 8; nt++)
        #pragma unroll
        for (int c = 0; c < 4; c++) acc[nt][c] = 0.0f;

    float xr[4], wpr[2], wnr[2]; float2 npr[2];

    if (ch < 36) {   // slabs of 8,8,8,4 rows
        slab_load<8>(x, w_pos, w_neg, n_param, i0, j0, tid, xr, wpr, wnr, npr);
        slab_store<8>(Ah[0], Al[0], Bh[0], Bl[0], tid, cG, xr, wpr, wnr, npr);
        __syncthreads();
        slab_load<8>(x, w_pos, w_neg, n_param, i0 + 8, j0, tid, xr, wpr, wnr, npr);
        slab_mma<8>(Ah[0], Al[0], Bh[0], Bl[0], wid, g, q, acc);
        slab_store<8>(Ah[1], Al[1], Bh[1], Bl[1], tid, cG, xr, wpr, wnr, npr);
        __syncthreads();
        slab_load<8>(x, w_pos, w_neg, n_param, i0 + 16, j0, tid, xr, wpr, wnr, npr);
        slab_mma<8>(Ah[1], Al[1], Bh[1], Bl[1], wid, g, q, acc);
        slab_store<8>(Ah[0], Al[0], Bh[0], Bl[0], tid, cG, xr, wpr, wnr, npr);
        __syncthreads();
        slab_load<4>(x, w_pos, w_neg, n_param, i0 + 24, j0, tid, xr, wpr, wnr, npr);
        slab_mma<8>(Ah[0], Al[0], Bh[0], Bl[0], wid, g, q, acc);
        slab_store<4>(Ah[1], Al[1], Bh[1], Bl[1], tid, cG, xr, wpr, wnr, npr);
        __syncthreads();
        slab_mma<4>(Ah[1], Al[1], Bh[1], Bl[1], wid, g, q, acc);
    } else {         // 16 rows: slabs of 8,8
        slab_load<8>(x, w_pos, w_neg, n_param, 1008, j0, tid, xr, wpr, wnr, npr);
        slab_store<8>(Ah[0], Al[0], Bh[0], Bl[0], tid, cG, xr, wpr, wnr, npr);
        __syncthreads();
        slab_load<8>(x, w_pos, w_neg, n_param, 1016, j0, tid, xr, wpr, wnr, npr);
        slab_mma<8>(Ah[0], Al[0], Bh[0], Bl[0], wid, g, q, acc);
        slab_store<8>(Ah[1], Al[1], Bh[1], Bl[1], tid, cG, xr, wpr, wnr, npr);
        __syncthreads();
        slab_mma<8>(Ah[1], Al[1], Bh[1], Bl[1], wid, g, q, acc);
    }

    // ---- store partials from fragments ----
    {
        float* outp = &g_partial[ch * (BATCH * NOUT)];
        const int b0 = 16 * wid + g;
        #pragma unroll
        for (int nt = 0; nt < 8; nt++) {
            int j = j0 + 8 * nt + 2 * q;
            *reinterpret_cast<float2*>(&outp[b0 * NOUT + j])       = make_float2(acc[nt][0], acc[nt][1]);
            *reinterpret_cast<float2*>(&outp[(b0 + 8) * NOUT + j]) = make_float2(acc[nt][2], acc[nt][3]);
        }
    }

    // ---- bias-term prefetch for the reduce slice (partial-independent) ----
    const int o = bid * 56 + tid;          // this block reduces 56 f4 (tid < 56)
    float4 bias = make_float4(0.0f, 0.0f, 0.0f, 0.0f);
    if (tid < 56 && o < OUTF4) {
        // bias row: vr = 2 exactly -> vr^(lg2 n + 1) = 2n -> term = (|b|+cG)*n
        const int j = (o * 4) & (NOUT - 1);
        float4 bp = *reinterpret_cast<const float4*>(&b_pos[j]);
        float4 bn = *reinterpret_cast<const float4*>(&b_neg[j]);
        const float* nrow = n_param + (size_t)NIN * (2 * NOUT);
        float4 n0 = *reinterpret_cast<const float4*>(&nrow[2 * j]);
        float4 n1 = *reinterpret_cast<const float4*>(&nrow[2 * j + 4]);
        bias.x = (fabsf(bp.x) + cG) * n0.x - (fabsf(bn.x) + cG) * n0.y;
        bias.y = (fabsf(bp.y) + cG) * n0.z - (fabsf(bn.y) + cG) * n0.w;
        bias.z = (fabsf(bp.z) + cG) * n1.x - (fabsf(bn.z) + cG) * n1.y;
        bias.w = (fabsf(bp.w) + cG) * n1.z - (fabsf(bn.w) + cG) * n1.w;
    }

    __threadfence();
    global_gate(&g_gate2, tid);

    // ---- distributed final reduction (all 296 CTAs; L2-hot partials) ----
    if (tid < 56 && o < OUTF4) {
        const float4* gp = reinterpret_cast<const float4*>(g_partial);
        float4 s = bias;
        #pragma unroll
        for (int c = 0; c < NCH; c++) {        // fixed order -> deterministic
            float4 v = gp[c * OUTF4 + o];
            s.x += v.x; s.y += v.y; s.z += v.z; s.w += v.w;
        }
        out[o] = s;
    }
}

// ---------------------------------------------------------------------------
extern "C" void kernel_launch(void* const* d_in, const int* in_sizes, int n_in,
                              void* d_out, int out_size) {
    const float* x       = (const float*)d_in[0];
    const float* w_pos   = (const float*)d_in[1];
    const float* w_neg   = (const float*)d_in[2];
    const float* b_pos   = (const float*)d_in[3];
    const float* b_neg   = (const float*)d_in[4];
    const float* n_param = (const float*)d_in[5];

    dim3 grid(NJT, NCH);     // 8 x 37 = 296 = 148*2, all co-resident at occ 2
    k_all<<<grid, 256>>>(x, w_pos, w_neg, n_param,
                         b_pos, b_neg, (float4*)d_out);
}